// round 3
// baseline (speedup 1.0000x reference)
#include <cuda_runtime.h>
#include <cstddef>

// 3D Haar wavelet (frames valid, h/w 'same' right-zero-pad), all 8 subbands fused.
// x: (2,3,16,256,256) f32. Out: LLL (2,3,15,256,256) then detail (2,3,105,256,256)
// detail order along axis2: LLH, LHL, LHH, HLL, HLH, HHL, HHH
//
// R2: 8-wide strips per thread (2 float4 + boundary scalar per row), all output
// stores via __stcs (evict-first) so the 189 MB write-once stream doesn't evict
// the 25 MB input from L2. Two 4-wide compute halves to bound register pressure.

#define NBC   6        // 2*3
#define NF    15
#define NH    256
#define NW    256
#define NW8   32       // NW/8
#define FRAME_STRIDE 65536   // 256*256
#define LLL_ELEMS 5898240    // 6*15*65536
#define S3 0.04419417382415922f  // 1/(16*sqrt(2))

__global__ void __launch_bounds__(256) haar3d_kernel(
    const float* __restrict__ x,
    float* __restrict__ out_lll,
    float* __restrict__ out_det)
{
    int idx = blockIdx.x * blockDim.x + threadIdx.x;
    // total threads = NBC*NF*NH*NW8 = 6*15*256*32 = 737,280 (grid exact)
    int wv   = idx & (NW8 - 1);
    int h    = (idx >> 5) & (NH - 1);
    int rest = idx >> 13;          // bc*NF + f
    int f    = rest % NF;
    int bc   = rest / NF;
    int w0   = wv << 3;

    const float* base = x + ((size_t)(bc * 16 + f)) * FRAME_STRIDE + h * NW + w0;
    const bool wtail = (wv == NW8 - 1);   // last strip: w0==248
    const bool hlast = (h == NH - 1);

    // rows: p[frame][height][lane 0..8]  (lane 8 = boundary scalar / zero pad)
    float p00[9], p01[9], p10[9], p11[9];

    #define LOAD_ROW(P, SRC) do {                                   \
        float4 _a = *(const float4*)(SRC);                          \
        float4 _b = *(const float4*)((SRC) + 4);                    \
        P[0]=_a.x; P[1]=_a.y; P[2]=_a.z; P[3]=_a.w;                 \
        P[4]=_b.x; P[5]=_b.y; P[6]=_b.z; P[7]=_b.w;                 \
        P[8] = wtail ? 0.f : (SRC)[8];                              \
    } while (0)

    LOAD_ROW(p00, base);
    LOAD_ROW(p10, base + FRAME_STRIDE);
    if (!hlast) {
        LOAD_ROW(p01, base + NW);
        LOAD_ROW(p11, base + FRAME_STRIDE + NW);
    } else {
        #pragma unroll
        for (int k = 0; k < 9; k++) { p01[k] = 0.f; p11[k] = 0.f; }
    }

    // output base pointers
    size_t plane = (size_t)h * NW + w0;
    float* oL = out_lll + ((size_t)(bc * NF + f)) * FRAME_STRIDE + plane;
    float* oD = out_det + ((size_t)(bc * 7 * NF + f)) * FRAME_STRIDE + plane;

    #pragma unroll
    for (int half = 0; half < 2; half++) {
        float4 vLLL, vLLH, vLHL, vLHH, vHLL, vHLH, vHHL, vHHH;
        float* rLLL = &vLLL.x; float* rLLH = &vLLH.x;
        float* rLHL = &vLHL.x; float* rLHH = &vLHH.x;
        float* rHLL = &vHLL.x; float* rHLH = &vHLH.x;
        float* rHHL = &vHHL.x; float* rHHH = &vHHH.x;

        #pragma unroll
        for (int kk = 0; kk < 4; kk++) {
            int k = half * 4 + kk;
            // w stage (low = a+b, high = b-a), per (frame, height) row
            float wl00 = p00[k] + p00[k+1], wh00 = p00[k+1] - p00[k];
            float wl01 = p01[k] + p01[k+1], wh01 = p01[k+1] - p01[k];
            float wl10 = p10[k] + p10[k+1], wh10 = p10[k+1] - p10[k];
            float wl11 = p11[k] + p11[k+1], wh11 = p11[k+1] - p11[k];
            // h stage per frame
            float q0LL = wl00 + wl01, q0LH = wh00 + wh01;
            float q0HL = wl01 - wl00, q0HH = wh01 - wh00;
            float q1LL = wl10 + wl11, q1LH = wh10 + wh11;
            float q1HL = wl11 - wl10, q1HH = wh11 - wh10;
            // f stage; labels (F,H,W)
            rLLL[kk] = S3 * (q0LL + q1LL);
            rLLH[kk] = S3 * (q0LH + q1LH);
            rLHL[kk] = S3 * (q0HL + q1HL);
            rLHH[kk] = S3 * (q0HH + q1HH);
            rHLL[kk] = S3 * (q1LL - q0LL);
            rHLH[kk] = S3 * (q1LH - q0LH);
            rHHL[kk] = S3 * (q1HL - q0HL);
            rHHH[kk] = S3 * (q1HH - q0HH);
        }

        int wo = half * 4;
        __stcs((float4*)(oL + wo), vLLL);
        __stcs((float4*)(oD + (size_t)0 * NF * FRAME_STRIDE + wo), vLLH);
        __stcs((float4*)(oD + (size_t)1 * NF * FRAME_STRIDE + wo), vLHL);
        __stcs((float4*)(oD + (size_t)2 * NF * FRAME_STRIDE + wo), vLHH);
        __stcs((float4*)(oD + (size_t)3 * NF * FRAME_STRIDE + wo), vHLL);
        __stcs((float4*)(oD + (size_t)4 * NF * FRAME_STRIDE + wo), vHLH);
        __stcs((float4*)(oD + (size_t)5 * NF * FRAME_STRIDE + wo), vHHL);
        __stcs((float4*)(oD + (size_t)6 * NF * FRAME_STRIDE + wo), vHHH);
    }
}

extern "C" void kernel_launch(void* const* d_in, const int* in_sizes, int n_in,
                              void* d_out, int out_size)
{
    const float* x = (const float*)d_in[0];
    float* out = (float*)d_out;
    float* out_lll = out;
    float* out_det = out + LLL_ELEMS;

    const int total = NBC * NF * NH * NW8;   // 737,280
    const int block = 256;
    const int grid = total / block;          // 2880
    haar3d_kernel<<<grid, block>>>(x, out_lll, out_det);
}

// round 5
// speedup vs baseline: 1.7907x; 1.7907x over previous
#include <cuda_runtime.h>
#include <cstddef>

// 3D Haar wavelet (frames valid, h/w 'same' right-zero-pad), all 8 subbands fused.
// x: (2,3,16,256,256) f32. Out: LLL (2,3,15,256,256) then detail (2,3,105,256,256)
// detail order along axis2: LLH, LHL, LHH, HLL, HLH, HHL, HHH
//
// R4 = R3 resubmitted (R3 bench was an infra failure, kernel never ran).
// R1 layout (4-wide contiguous strips -> 512B fully-coalesced warp stores;
// R2's 8-wide strips caused 32B-stride partial-sector writes and regressed 2x).
// Single change vs R1: __stcs (evict-first) on the 189 MB write-once output
// stream so it doesn't evict the 25 MB input (4x reuse) from L2.

#define NBC   6        // 2*3
#define NF    15
#define NH    256
#define NW    256
#define NW4   64       // NW/4
#define FRAME_STRIDE 65536   // 256*256
#define LLL_ELEMS 5898240    // 6*15*65536
#define S3 0.04419417382415922f  // 1/(16*sqrt(2))

__global__ void __launch_bounds__(256) haar3d_kernel(
    const float* __restrict__ x,
    float* __restrict__ out_lll,
    float* __restrict__ out_det)
{
    int idx = blockIdx.x * blockDim.x + threadIdx.x;
    // total threads = NBC*NF*NH*NW4 = 6*15*256*64 = 1,474,560 (grid exact)
    int wv   = idx & (NW4 - 1);
    int h    = (idx >> 6) & (NH - 1);
    int rest = idx >> 14;          // bc*NF + f
    int f    = rest % NF;
    int bc   = rest / NF;
    int w0   = wv << 2;

    const float* base = x + ((size_t)(bc * 16 + f)) * FRAME_STRIDE + h * NW + w0;
    const bool wtail = (wv == NW4 - 1);   // last strip: w0==252
    const bool hlast = (h == NH - 1);

    // corners: p[frame][height][lane 0..4]  (lane 4 = boundary scalar / zero pad)
    float p00[5], p01[5], p10[5], p11[5];

    {
        float4 v = *(const float4*)(base);
        p00[0]=v.x; p00[1]=v.y; p00[2]=v.z; p00[3]=v.w;
        p00[4] = wtail ? 0.f : base[4];
    }
    {
        float4 v = *(const float4*)(base + FRAME_STRIDE);
        p10[0]=v.x; p10[1]=v.y; p10[2]=v.z; p10[3]=v.w;
        p10[4] = wtail ? 0.f : base[FRAME_STRIDE + 4];
    }
    if (!hlast) {
        float4 v = *(const float4*)(base + NW);
        p01[0]=v.x; p01[1]=v.y; p01[2]=v.z; p01[3]=v.w;
        p01[4] = wtail ? 0.f : base[NW + 4];
        float4 u = *(const float4*)(base + FRAME_STRIDE + NW);
        p11[0]=u.x; p11[1]=u.y; p11[2]=u.z; p11[3]=u.w;
        p11[4] = wtail ? 0.f : base[FRAME_STRIDE + NW + 4];
    } else {
        #pragma unroll
        for (int k = 0; k < 5; k++) { p01[k] = 0.f; p11[k] = 0.f; }
    }

    float4 oLLL, oLLH, oLHL, oLHH, oHLL, oHLH, oHHL, oHHH;
    float* rLLL = &oLLL.x; float* rLLH = &oLLH.x;
    float* rLHL = &oLHL.x; float* rLHH = &oLHH.x;
    float* rHLL = &oHLL.x; float* rHLH = &oHLH.x;
    float* rHHL = &oHHL.x; float* rHHH = &oHHH.x;

    #pragma unroll
    for (int k = 0; k < 4; k++) {
        // w stage (low = a+b, high = b-a), per (frame, height) row
        float wl00 = p00[k] + p00[k+1], wh00 = p00[k+1] - p00[k];
        float wl01 = p01[k] + p01[k+1], wh01 = p01[k+1] - p01[k];
        float wl10 = p10[k] + p10[k+1], wh10 = p10[k+1] - p10[k];
        float wl11 = p11[k] + p11[k+1], wh11 = p11[k+1] - p11[k];
        // h stage per frame
        float q0LL = wl00 + wl01, q0LH = wh00 + wh01;
        float q0HL = wl01 - wl00, q0HH = wh01 - wh00;
        float q1LL = wl10 + wl11, q1LH = wh10 + wh11;
        float q1HL = wl11 - wl10, q1HH = wh11 - wh10;
        // f stage; labels (F,H,W)
        rLLL[k] = S3 * (q0LL + q1LL);
        rLLH[k] = S3 * (q0LH + q1LH);
        rLHL[k] = S3 * (q0HL + q1HL);
        rLHH[k] = S3 * (q0HH + q1HH);
        rHLL[k] = S3 * (q1LL - q0LL);
        rHLH[k] = S3 * (q1LH - q0LH);
        rHHL[k] = S3 * (q1HL - q0HL);
        rHHH[k] = S3 * (q1HH - q0HH);
    }

    size_t plane = (size_t)h * NW + w0;
    // LLL: (bc, f, h, w)
    __stcs((float4*)(out_lll + ((size_t)(bc * NF + f)) * FRAME_STRIDE + plane), oLLL);
    // detail: (bc, s*15 + f, h, w), s in {LLH,LHL,LHH,HLL,HLH,HHL,HHH}
    float* dbase = out_det + ((size_t)(bc * 7 * NF + f)) * FRAME_STRIDE + plane;
    __stcs((float4*)(dbase + (size_t)0 * NF * FRAME_STRIDE), oLLH);
    __stcs((float4*)(dbase + (size_t)1 * NF * FRAME_STRIDE), oLHL);
    __stcs((float4*)(dbase + (size_t)2 * NF * FRAME_STRIDE), oLHH);
    __stcs((float4*)(dbase + (size_t)3 * NF * FRAME_STRIDE), oHLL);
    __stcs((float4*)(dbase + (size_t)4 * NF * FRAME_STRIDE), oHLH);
    __stcs((float4*)(dbase + (size_t)5 * NF * FRAME_STRIDE), oHHL);
    __stcs((float4*)(dbase + (size_t)6 * NF * FRAME_STRIDE), oHHH);
}

extern "C" void kernel_launch(void* const* d_in, const int* in_sizes, int n_in,
                              void* d_out, int out_size)
{
    const float* x = (const float*)d_in[0];
    float* out = (float*)d_out;
    float* out_lll = out;
    float* out_det = out + LLL_ELEMS;

    const int total = NBC * NF * NH * NW4;   // 1,474,560
    const int block = 256;
    const int grid = total / block;          // 5760
    haar3d_kernel<<<grid, block>>>(x, out_lll, out_det);
}

// round 6
// speedup vs baseline: 1.8656x; 1.0419x over previous
#include <cuda_runtime.h>
#include <cstddef>

// 3D Haar wavelet (frames valid, h/w 'same' right-zero-pad), all 8 subbands fused.
// x: (2,3,16,256,256) f32. Out: LLL (2,3,15,256,256) then detail (2,3,105,256,256)
// detail order along axis2: LLH, LHL, LHH, HLL, HLH, HHL, HHH
//
// R5: h-pairing. Each thread produces output rows (h0, h0+1) for one 4-wide
// strip, loading 3 input rows per frame (6 total) instead of 4 — the shared
// middle row is loaded once. -25% loads / L2 read traffic vs R4; store pattern
// identical to R4 (4-wide contiguous strips -> 512B coalesced warp stores),
// all stores __stcs (R4's proven win: write-once stream drains early).

#define NBC   6        // 2*3
#define NF    15
#define NH    256
#define NW    256
#define NW4   64       // NW/4
#define NHP   128      // NH/2 output-row pairs
#define FRAME_STRIDE 65536   // 256*256
#define LLL_ELEMS 5898240    // 6*15*65536
#define S3 0.04419417382415922f  // 1/(16*sqrt(2))

__global__ void __launch_bounds__(256) haar3d_kernel(
    const float* __restrict__ x,
    float* __restrict__ out_lll,
    float* __restrict__ out_det)
{
    int idx = blockIdx.x * blockDim.x + threadIdx.x;
    // total threads = NBC*NF*NHP*NW4 = 6*15*128*64 = 737,280 (grid exact)
    int wv   = idx & (NW4 - 1);
    int hp   = (idx >> 6) & (NHP - 1);
    int rest = idx >> 13;          // bc*NF + f
    int f    = rest % NF;
    int bc   = rest / NF;
    int w0   = wv << 2;
    int h0   = hp << 1;            // first output row of the pair (0..254)

    const float* base = x + ((size_t)(bc * 16 + f)) * FRAME_STRIDE + h0 * NW + w0;
    const bool wtail = (wv == NW4 - 1);   // last strip: w0==252
    const bool hend  = (hp == NHP - 1);   // h0==254 -> row h0+2 is zero pad

    // raw rows: frame a = f, frame b = f+1; rows 0..2 = h0, h0+1, h0+2
    float a0[5], a1[5], a2[5], b0[5], b1[5], b2[5];

    #define LOAD_ROW(P, SRC) do {                                   \
        float4 _v = *(const float4*)(SRC);                          \
        P[0]=_v.x; P[1]=_v.y; P[2]=_v.z; P[3]=_v.w;                 \
        P[4] = wtail ? 0.f : (SRC)[4];                              \
    } while (0)

    LOAD_ROW(a0, base);
    LOAD_ROW(a1, base + NW);
    LOAD_ROW(b0, base + FRAME_STRIDE);
    LOAD_ROW(b1, base + FRAME_STRIDE + NW);
    if (!hend) {
        LOAD_ROW(a2, base + 2 * NW);
        LOAD_ROW(b2, base + FRAME_STRIDE + 2 * NW);
    } else {
        #pragma unroll
        for (int k = 0; k < 5; k++) { a2[k] = 0.f; b2[k] = 0.f; }
    }

    // output bases (row h0); row h0+1 = +NW
    size_t plane = (size_t)h0 * NW + w0;
    float* oL = out_lll + ((size_t)(bc * NF + f)) * FRAME_STRIDE + plane;
    float* oD = out_det + ((size_t)(bc * 7 * NF + f)) * FRAME_STRIDE + plane;

    // Compute + store all 8 subbands for one output row.
    // (alo,ahi) = frame f rows h,h+1 ; (blo,bhi) = frame f+1 rows h,h+1
    #define DO_ROW(ALO, AHI, BLO, BHI, ROWOFF) do {                              \
        float4 vLLL, vLLH, vLHL, vLHH, vHLL, vHLH, vHHL, vHHH;                   \
        float* rLLL=&vLLL.x; float* rLLH=&vLLH.x; float* rLHL=&vLHL.x;           \
        float* rLHH=&vLHH.x; float* rHLL=&vHLL.x; float* rHLH=&vHLH.x;           \
        float* rHHL=&vHHL.x; float* rHHH=&vHHH.x;                                \
        _Pragma("unroll")                                                        \
        for (int k = 0; k < 4; k++) {                                            \
            float wl00 = ALO[k] + ALO[k+1], wh00 = ALO[k+1] - ALO[k];            \
            float wl01 = AHI[k] + AHI[k+1], wh01 = AHI[k+1] - AHI[k];            \
            float wl10 = BLO[k] + BLO[k+1], wh10 = BLO[k+1] - BLO[k];            \
            float wl11 = BHI[k] + BHI[k+1], wh11 = BHI[k+1] - BHI[k];            \
            float q0LL = wl00 + wl01, q0LH = wh00 + wh01;                        \
            float q0HL = wl01 - wl00, q0HH = wh01 - wh00;                        \
            float q1LL = wl10 + wl11, q1LH = wh10 + wh11;                        \
            float q1HL = wl11 - wl10, q1HH = wh11 - wh10;                        \
            rLLL[k] = S3 * (q0LL + q1LL);                                        \
            rLLH[k] = S3 * (q0LH + q1LH);                                        \
            rLHL[k] = S3 * (q0HL + q1HL);                                        \
            rLHH[k] = S3 * (q0HH + q1HH);                                        \
            rHLL[k] = S3 * (q1LL - q0LL);                                        \
            rHLH[k] = S3 * (q1LH - q0LH);                                        \
            rHHL[k] = S3 * (q1HL - q0HL);                                        \
            rHHH[k] = S3 * (q1HH - q0HH);                                        \
        }                                                                        \
        __stcs((float4*)(oL + (ROWOFF)), vLLL);                                  \
        __stcs((float4*)(oD + (size_t)0 * NF * FRAME_STRIDE + (ROWOFF)), vLLH);  \
        __stcs((float4*)(oD + (size_t)1 * NF * FRAME_STRIDE + (ROWOFF)), vLHL);  \
        __stcs((float4*)(oD + (size_t)2 * NF * FRAME_STRIDE + (ROWOFF)), vLHH);  \
        __stcs((float4*)(oD + (size_t)3 * NF * FRAME_STRIDE + (ROWOFF)), vHLL);  \
        __stcs((float4*)(oD + (size_t)4 * NF * FRAME_STRIDE + (ROWOFF)), vHLH);  \
        __stcs((float4*)(oD + (size_t)5 * NF * FRAME_STRIDE + (ROWOFF)), vHHL);  \
        __stcs((float4*)(oD + (size_t)6 * NF * FRAME_STRIDE + (ROWOFF)), vHHH);  \
    } while (0)

    DO_ROW(a0, a1, b0, b1, 0);     // output row h0   (rows h0, h0+1)
    DO_ROW(a1, a2, b1, b2, NW);    // output row h0+1 (rows h0+1, h0+2)

    #undef DO_ROW
    #undef LOAD_ROW
}

extern "C" void kernel_launch(void* const* d_in, const int* in_sizes, int n_in,
                              void* d_out, int out_size)
{
    const float* x = (const float*)d_in[0];
    float* out = (float*)d_out;
    float* out_lll = out;
    float* out_det = out + LLL_ELEMS;

    const int total = NBC * NF * NHP * NW4;  // 737,280
    const int block = 256;
    const int grid = total / block;          // 2880
    haar3d_kernel<<<grid, block>>>(x, out_lll, out_det);
}